// round 3
// baseline (speedup 1.0000x reference)
#include <cuda_runtime.h>
#include <math_constants.h>

// Problem constants
#define BATCH 4
#define SLEN  32768
#define C1    128      // HID/4
#define C2    256      // HID/2
#define HID   512
#define L1LEN 16384    // SLEN/2
#define L2LEN 8192
#define L3LEN 4096
#define VOCAB 2048
#define KCB   4

// ------------------- device scratch (no allocations allowed) -------------------
// NOTE: these are ONLY referenced from device code. Passing them as kernel
// arguments from host passes the host-shadow address (silently ATS-resolved on
// GB300) — that was the round-1/2 bug.
__device__ __align__(16) float g_conv1[BATCH * C1 * L1LEN];     // [B,C1,L1]
__device__ __align__(16) float g_conv2[BATCH * C2 * L2LEN];     // [B,C2,L2]
__device__ __align__(16) float g_feats[BATCH * L3LEN * HID];    // [B,L,H]
__device__ __align__(16) float g_c2[KCB * VOCAB];
__device__ int   g_tokens[BATCH * KCB * L3LEN];

// ------------------- conv1: Cin=1, k=7, s=2, pad=3, relu -------------------
__global__ void conv1_kernel(const float* __restrict__ x,
                             const float* __restrict__ w,
                             const float* __restrict__ bias) {
    int idx = blockIdx.x * blockDim.x + threadIdx.x;       // B*C1*L1 = 8,388,608
    int l = idx & (L1LEN - 1);
    int c = (idx >> 14) & (C1 - 1);
    int b = idx >> 21;
    const float* xb = x + (size_t)b * SLEN;
    float acc = bias[c];
    int base = 2 * l - 3;
#pragma unroll
    for (int t = 0; t < 7; t++) {
        int p = base + t;
        float xv = (p >= 0 && p < SLEN) ? __ldg(xb + p) : 0.f;
        acc = fmaf(__ldg(w + c * 7 + t), xv, acc);
    }
    g_conv1[idx] = fmaxf(acc, 0.f);
}

// ------------------- generic conv k=7 s=2 pad=3, tiled implicit GEMM -------------------
// STAGE==2: g_conv1 -> g_conv2 ([B,CO,LOUT]), relu
// STAGE==3: g_conv2 -> g_feats ([B,LOUT,CO] transposed), no relu
// block: 128 threads, tile 32 co x 32 l.
template <int CI, int CO, int LOUT, bool RELU, bool TRANS_OUT, int STAGE>
__global__ void conv_tiled_kernel(const float* __restrict__ w,
                                  const float* __restrict__ bias) {
    const float* in  = (STAGE == 2) ? g_conv1 : g_conv2;
    float*       out = (STAGE == 2) ? g_conv2 : g_feats;

    const int LIN = 2 * LOUT;
    __shared__ float in_s[8][72];          // 8 ci x 69 positions (padded)
    __shared__ float w_s[8 * 7 * 32];      // [ci][t][co]

    int tid = threadIdx.x;
    int l0  = blockIdx.x * 32;
    int co0 = blockIdx.y * 32;
    int b   = blockIdx.z;
    int co  = tid & 31;
    int lg  = tid >> 5;                    // 0..3

    float acc[8];
#pragma unroll
    for (int j = 0; j < 8; j++) acc[j] = 0.f;

    for (int ci0 = 0; ci0 < CI; ci0 += 8) {
        __syncthreads();
        for (int i = tid; i < 8 * 70; i += 128) {
            int ci = i / 70, p = i % 70;
            int pg = 2 * l0 - 3 + p;
            float v = 0.f;
            if (p < 69 && pg >= 0 && pg < LIN)
                v = in[((size_t)b * CI + ci0 + ci) * LIN + pg];
            in_s[ci][p] = v;
        }
        for (int i = tid; i < 8 * 7 * 32; i += 128) {
            int co_i = i & 31;
            int rest = i >> 5;              // ci*7 + t
            int t = rest % 7, ci = rest / 7;
            w_s[rest * 32 + co_i] = w[((size_t)(co0 + co_i) * CI + ci0 + ci) * 7 + t];
        }
        __syncthreads();

#pragma unroll
        for (int ci = 0; ci < 8; ci++) {
            float xv[21];
#pragma unroll
            for (int p = 0; p < 21; p++) xv[p] = in_s[ci][16 * lg + p];
#pragma unroll
            for (int t = 0; t < 7; t++) {
                float wv = w_s[(ci * 7 + t) * 32 + co];
#pragma unroll
                for (int j = 0; j < 8; j++)
                    acc[j] = fmaf(wv, xv[2 * j + t], acc[j]);
            }
        }
    }

    float bv = bias[co0 + co];
#pragma unroll
    for (int j = 0; j < 8; j++) {
        float r = acc[j] + bv;
        if (RELU) r = fmaxf(r, 0.f);
        int l = l0 + lg * 8 + j;
        if (TRANS_OUT)
            out[((size_t)b * LOUT + l) * CO + co0 + co] = r;   // [B,L,CO]
        else
            out[((size_t)b * CO + co0 + co) * LOUT + l] = r;   // [B,CO,L]
    }
}

// ------------------- c2: per-codebook-row squared norms -------------------
__global__ void c2_kernel(const float* __restrict__ cb) {
    int row = blockIdx.x * 8 + (threadIdx.x >> 5);   // K*V = 8192 rows
    int lane = threadIdx.x & 31;
    const float* p = cb + (size_t)row * HID;
    float s = 0.f;
#pragma unroll 4
    for (int h = lane; h < HID; h += 32) {
        float v = p[h];
        s = fmaf(v, v, s);
    }
#pragma unroll
    for (int off = 16; off; off >>= 1)
        s += __shfl_xor_sync(0xffffffffu, s, off);
    if (lane == 0) g_c2[row] = s;
}

// ------------------- fused GEMM + argmin -------------------
__global__ __launch_bounds__(256) void argmin_kernel(const float* __restrict__ cb) {
    __shared__ float a_s[16][64];
    __shared__ float b_s[16][64];
    __shared__ float c2_s[64];

    int tid = threadIdx.x;
    int l0 = blockIdx.x * 64;
    int k  = blockIdx.y;
    int b  = blockIdx.z;

    const float* A  = g_feats + ((size_t)b * L3LEN + l0) * HID;
    const float* Bm = cb + (size_t)k * VOCAB * HID;

    int tr = tid >> 4, tc = tid & 15;
    int r = tid >> 2, q = tid & 3;

    float minv[4];
    int   mini[4];
#pragma unroll
    for (int i = 0; i < 4; i++) { minv[i] = CUDART_INF_F; mini[i] = 0; }

    for (int v0 = 0; v0 < VOCAB; v0 += 64) {
        float acc[4][4];
#pragma unroll
        for (int i = 0; i < 4; i++)
#pragma unroll
            for (int j = 0; j < 4; j++) acc[i][j] = 0.f;

        for (int h0 = 0; h0 < HID; h0 += 16) {
            __syncthreads();
            float4 av = *(const float4*)(A + (size_t)r * HID + h0 + q * 4);
            a_s[q * 4 + 0][r] = av.x; a_s[q * 4 + 1][r] = av.y;
            a_s[q * 4 + 2][r] = av.z; a_s[q * 4 + 3][r] = av.w;
            float4 bv = *(const float4*)(Bm + (size_t)(v0 + r) * HID + h0 + q * 4);
            b_s[q * 4 + 0][r] = bv.x; b_s[q * 4 + 1][r] = bv.y;
            b_s[q * 4 + 2][r] = bv.z; b_s[q * 4 + 3][r] = bv.w;
            __syncthreads();

#pragma unroll
            for (int kk = 0; kk < 16; kk++) {
                float4 ar = ((const float4*)&a_s[kk][0])[tr];
                float4 br = ((const float4*)&b_s[kk][0])[tc];
                acc[0][0] = fmaf(ar.x, br.x, acc[0][0]);
                acc[0][1] = fmaf(ar.x, br.y, acc[0][1]);
                acc[0][2] = fmaf(ar.x, br.z, acc[0][2]);
                acc[0][3] = fmaf(ar.x, br.w, acc[0][3]);
                acc[1][0] = fmaf(ar.y, br.x, acc[1][0]);
                acc[1][1] = fmaf(ar.y, br.y, acc[1][1]);
                acc[1][2] = fmaf(ar.y, br.z, acc[1][2]);
                acc[1][3] = fmaf(ar.y, br.w, acc[1][3]);
                acc[2][0] = fmaf(ar.z, br.x, acc[2][0]);
                acc[2][1] = fmaf(ar.z, br.y, acc[2][1]);
                acc[2][2] = fmaf(ar.z, br.z, acc[2][2]);
                acc[2][3] = fmaf(ar.z, br.w, acc[2][3]);
                acc[3][0] = fmaf(ar.w, br.x, acc[3][0]);
                acc[3][1] = fmaf(ar.w, br.y, acc[3][1]);
                acc[3][2] = fmaf(ar.w, br.z, acc[3][2]);
                acc[3][3] = fmaf(ar.w, br.w, acc[3][3]);
            }
        }
        __syncthreads();
        if (tid < 64) c2_s[tid] = g_c2[k * VOCAB + v0 + tid];
        __syncthreads();

#pragma unroll
        for (int i = 0; i < 4; i++) {
#pragma unroll
            for (int j = 0; j < 4; j++) {
                float d = c2_s[tc * 4 + j] - 2.f * acc[i][j];
                int vi = v0 + tc * 4 + j;
                if (d < minv[i]) { minv[i] = d; mini[i] = vi; }
            }
        }
    }

#pragma unroll
    for (int off = 8; off; off >>= 1) {
#pragma unroll
        for (int i = 0; i < 4; i++) {
            float ov = __shfl_xor_sync(0xffffffffu, minv[i], off, 16);
            int   oi = __shfl_xor_sync(0xffffffffu, mini[i], off, 16);
            if (ov < minv[i] || (ov == minv[i] && oi < mini[i])) {
                minv[i] = ov; mini[i] = oi;
            }
        }
    }
    if (tc == 0) {
#pragma unroll
        for (int i = 0; i < 4; i++)
            g_tokens[((size_t)b * KCB + k) * L3LEN + l0 + tr * 4 + i] = mini[i];
    }
}

// ------------------- embedding gather + mean over K -------------------
__global__ void emb_kernel(const float* __restrict__ embedding, float* __restrict__ out) {
    int bl = blockIdx.x;               // B*L = 16384
    int b = bl >> 12;
    int l = bl & (L3LEN - 1);
    int t0 = g_tokens[((size_t)b * KCB + 0) * L3LEN + l];
    int t1 = g_tokens[((size_t)b * KCB + 1) * L3LEN + l];
    int t2 = g_tokens[((size_t)b * KCB + 2) * L3LEN + l];
    int t3 = g_tokens[((size_t)b * KCB + 3) * L3LEN + l];
    const float4* e0 = (const float4*)(embedding + (size_t)t0 * HID);
    const float4* e1 = (const float4*)(embedding + (size_t)t1 * HID);
    const float4* e2 = (const float4*)(embedding + (size_t)t2 * HID);
    const float4* e3 = (const float4*)(embedding + (size_t)t3 * HID);
    int h = threadIdx.x;               // 128 threads x float4 = 512 floats
    float4 v0 = e0[h], v1 = e1[h], v2 = e2[h], v3 = e3[h];
    float4 rr;
    rr.x = 0.25f * (v0.x + v1.x + v2.x + v3.x);
    rr.y = 0.25f * (v0.y + v1.y + v2.y + v3.y);
    rr.z = 0.25f * (v0.z + v1.z + v2.z + v3.z);
    rr.w = 0.25f * (v0.w + v1.w + v2.w + v3.w);
    ((float4*)(out + ((size_t)b * L3LEN + l) * HID))[h] = rr;
}

// ------------------- tokens (int) -> output (float) -------------------
__global__ void tok2f_kernel(float* __restrict__ out) {
    int i = blockIdx.x * blockDim.x + threadIdx.x;
    if (i < BATCH * KCB * L3LEN) out[i] = (float)g_tokens[i];
}

// ------------------- launch -------------------
extern "C" void kernel_launch(void* const* d_in, const int* in_sizes, int n_in,
                              void* d_out, int out_size) {
    // Bind inputs by UNIQUE element count (robust to metadata ordering)
    const float* audio = 0; const float* w1 = 0; const float* b1 = 0;
    const float* w2 = 0; const float* b2 = 0; const float* w3 = 0; const float* b3 = 0;
    const float* codebook = 0; const float* embedding = 0;
    for (int i = 0; i < n_in; i++) {
        const float* p = (const float*)d_in[i];
        switch (in_sizes[i]) {
            case BATCH * SLEN:        audio = p; break;      // 131072
            case C1 * 1 * 7:          w1 = p; break;         // 896
            case C1:                  b1 = p; break;         // 128
            case C2 * C1 * 7:         w2 = p; break;         // 229376
            case C2:                  b2 = p; break;         // 256
            case HID * C2 * 7:        w3 = p; break;         // 917504
            case HID:                 b3 = p; break;         // 512
            case KCB * VOCAB * HID:   codebook = p; break;   // 4194304
            case VOCAB * HID:         embedding = p; break;  // 1048576
            default: break;
        }
    }

    // conv stack (scratch buffers bound in DEVICE code via STAGE)
    conv1_kernel<<<(BATCH * C1 * L1LEN) / 256, 256>>>(audio, w1, b1);
    {
        dim3 grid(L2LEN / 32, C2 / 32, BATCH);
        conv_tiled_kernel<C1, C2, L2LEN, true, false, 2><<<grid, 128>>>(w2, b2);
    }
    {
        dim3 grid(L3LEN / 32, HID / 32, BATCH);
        conv_tiled_kernel<C2, HID, L3LEN, false, true, 3><<<grid, 128>>>(w3, b3);
    }

    // codebook norms + fused GEMM/argmin
    c2_kernel<<<(KCB * VOCAB) / 8, 256>>>(codebook);
    {
        dim3 grid(L3LEN / 64, KCB, BATCH);
        argmin_kernel<<<grid, 256>>>(codebook);
    }

    // outputs: tokens (as float) then emb, adapt to out_size
    const int TOK = BATCH * KCB * L3LEN;          // 65536
    const int EMB = BATCH * L3LEN * HID;          // 8388608
    float* out = (float*)d_out;
    if (out_size >= TOK + EMB) {
        tok2f_kernel<<<(TOK + 255) / 256, 256>>>(out);
        emb_kernel<<<BATCH * L3LEN, 128>>>(embedding, out + TOK);
    } else if (out_size >= EMB) {
        emb_kernel<<<BATCH * L3LEN, 128>>>(embedding, out);
    } else {
        tok2f_kernel<<<(TOK + 255) / 256, 256>>>(out);
    }
}